// round 4
// baseline (speedup 1.0000x reference)
#include <cuda_runtime.h>

// x: [32, 256, 64, 64] f32; weight: [256, 256, 3, 3] f32; bias: [256] f32
// out: [32, 256, 1, 1] f32   (spatial = 128*128 = 16384)
#define B_   32
#define C_   256
#define O_   256
#define HW_  4096            // 64*64
#define BC_  (B_ * C_)       // 8192
#define CO_  (C_ * O_)       // 65536
#define WPREP_BLOCKS (CO_ / 256)          // 256
#define NPROD (BC_ + WPREP_BLOCKS)        // 8448 producer blocks
#define NTOTAL (NPROD + O_)               // + 256 gemm blocks = 8704

// Scratch (no allocations allowed). Zero-initialized at module load;
// counters are reset by the last consumer block each launch (replay-safe).
__device__ float4 g_statsT[BC_];  // [c][b] -> (T, R0, C0, x00)
__device__ float4 g_wcatT[CO_];   // [o][c] -> (Wsum, -Wkh0, -Wkw0, W00)
__device__ unsigned int g_cnt;    // producer completion counter
__device__ unsigned int g_cnt2;   // consumer completion counter (for reset)

// ---------------------------------------------------------------------------
// One fused launch:
//   blocks [0, 8192)      : per-(b,c) image stats (the 134 MB roofline stream)
//   blocks [8192, 8448)   : weight folding
//   blocks [8448, 8704)   : micro-GEMM, spin-wait until all producers done
// ---------------------------------------------------------------------------
__global__ void __launch_bounds__(256) fused_kernel(const float* __restrict__ x,
                                                    const float* __restrict__ w,
                                                    const float* __restrict__ bias,
                                                    float* __restrict__ out) {
    const int t = threadIdx.x;

    if (blockIdx.x < BC_) {
        // ---------------- stats: one block per (b,c) 16 KB image ----------
        const int bc = blockIdx.x;
        const float4* __restrict__ p4 =
            reinterpret_cast<const float4*>(x + (size_t)bc * HW_);

        float s = 0.f, r0 = 0.f, c0 = 0.f, v00 = 0.f;

        #pragma unroll
        for (int i = 0; i < 4; i++) {
            const int j = t + i * 256;        // float4 index 0..1023
            float4 v = p4[j];
            float vs = v.x + v.y + v.z + v.w;
            s += vs;
            if (j < 16)          r0 += vs;    // row 0 = first 64 elems
            if ((j & 15) == 0)   c0 += v.x;   // col 0 = elem % 64 == 0
            if (j == 0)          v00 = v.x;
        }

        #pragma unroll
        for (int off = 16; off > 0; off >>= 1) {
            s  += __shfl_xor_sync(0xFFFFFFFFu, s,  off);
            r0 += __shfl_xor_sync(0xFFFFFFFFu, r0, off);
            c0 += __shfl_xor_sync(0xFFFFFFFFu, c0, off);
        }

        __shared__ float ss[8], sr[8], sc[8];
        __shared__ float sv00;
        const int warp = t >> 5, lane = t & 31;
        if (t == 0) sv00 = v00;
        if (lane == 0) { ss[warp] = s; sr[warp] = r0; sc[warp] = c0; }
        __syncthreads();

        if (warp == 0) {
            float fs = (lane < 8) ? ss[lane] : 0.f;
            float fr = (lane < 8) ? sr[lane] : 0.f;
            float fc = (lane < 8) ? sc[lane] : 0.f;
            #pragma unroll
            for (int off = 4; off > 0; off >>= 1) {
                fs += __shfl_xor_sync(0xFFFFFFFFu, fs, off);
                fr += __shfl_xor_sync(0xFFFFFFFFu, fr, off);
                fc += __shfl_xor_sync(0xFFFFFFFFu, fc, off);
            }
            if (lane == 0) {
                const int b = bc >> 8;
                const int c = bc & 255;
                g_statsT[c * B_ + b] = make_float4(fs, fr, fc, sv00);
                __threadfence();                      // release stats
                atomicAdd(&g_cnt, 1u);
            }
        }
    } else if (blockIdx.x < NPROD) {
        // ---------------- weight folding ----------------------------------
        const int i = (blockIdx.x - BC_) * 256 + t;   // i = c*256 + o
        const int c = i >> 8;
        const int o = i & 255;
        const float* p = w + (size_t)i * 9;
        float w00 = p[0], w01 = p[1], w02 = p[2];
        float w10 = p[3], w11 = p[4], w12 = p[5];
        float w20 = p[6], w21 = p[7], w22 = p[8];
        float wsum = ((w00 + w01) + (w02 + w10)) + ((w11 + w12) + (w20 + w21)) + w22;
        float wkh0 = w00 + w01 + w02;   // kh == 0 row
        float wkw0 = w00 + w10 + w20;   // kw == 0 col
        g_wcatT[o * C_ + c] = make_float4(wsum, -wkh0, -wkw0, w00);
        __threadfence();                              // release wcat (per thread)
        __syncthreads();
        if (t == 0) atomicAdd(&g_cnt, 1u);
    } else {
        // ---------------- micro-GEMM consumer ------------------------------
        // S[b,o] = sum_c dot4(statsT[c][b], wcatT[o][c]); one block per o.
        const int o = blockIdx.x - NPROD;

        if (t == 0) {
            volatile unsigned int* cnt = &g_cnt;
            while (*cnt < (unsigned int)NPROD) { }
            __threadfence();                          // acquire
        }
        __syncthreads();

        // counter reset for next graph replay (after whole block passed spin)
        if (t == 0) {
            unsigned int old = atomicAdd(&g_cnt2, 1u);
            if (old == O_ - 1u) {                     // last consumer block
                atomicExch(&g_cnt, 0u);
                atomicExch(&g_cnt2, 0u);
            }
        }

        __shared__ float4 wsm[C_];
        __shared__ float  red[8][33];

        wsm[t] = g_wcatT[o * C_ + t];
        __syncthreads();

        const int b  = t & 31;   // lane = batch
        const int cg = t >> 5;   // warp = c-group of 32
        const int cbase = cg * 32;

        float acc0 = 0.f, acc1 = 0.f;

        #pragma unroll 8
        for (int k = 0; k < 32; k += 2) {
            const int c = cbase + k;
            float4 a0 = g_statsT[c * B_ + b];
            float4 w0 = wsm[c];
            float4 a1 = g_statsT[(c + 1) * B_ + b];
            float4 w1 = wsm[c + 1];
            acc0 = fmaf(a0.x, w0.x, acc0);
            acc1 = fmaf(a1.x, w1.x, acc1);
            acc0 = fmaf(a0.y, w0.y, acc0);
            acc1 = fmaf(a1.y, w1.y, acc1);
            acc0 = fmaf(a0.z, w0.z, acc0);
            acc1 = fmaf(a1.z, w1.z, acc1);
            acc0 = fmaf(a0.w, w0.w, acc0);
            acc1 = fmaf(a1.w, w1.w, acc1);
        }

        red[cg][b] = acc0 + acc1;
        __syncthreads();

        if (t < 32) {
            float s = 0.f;
            #pragma unroll
            for (int g = 0; g < 8; g++) s += red[g][t];
            out[t * O_ + o] = 2.0f * (s * (1.0f / 16384.0f) + bias[o]);
        }
    }
}

// ---------------------------------------------------------------------------
extern "C" void kernel_launch(void* const* d_in, const int* in_sizes, int n_in,
                              void* d_out, int out_size) {
    const float* x    = (const float*)d_in[0];
    const float* wgt  = (const float*)d_in[1];
    const float* bias = (const float*)d_in[2];
    float* out        = (float*)d_out;

    fused_kernel<<<NTOTAL, 256>>>(x, wgt, bias, out);
}

// round 6
// speedup vs baseline: 1.0998x; 1.0998x over previous
#include <cuda_runtime.h>

// x: [32, 256, 64, 64] f32; weight: [256, 256, 3, 3] f32; bias: [256] f32
// out: [32, 256, 1, 1] f32   (spatial = 128*128 = 16384)
#define B_   32
#define C_   256
#define O_   256
#define HW_  4096            // 64*64
#define BC_  (B_ * C_)       // 8192
#define CO_  (C_ * O_)       // 65536
#define WPREP_BLOCKS (CO_ / 256)   // 256
#define QSPLIT 4                   // c-dimension split in gemm
#define CQ_ (C_ / QSPLIT)          // 64 channels per gemm block

// Scratch (no allocations allowed). g_done zero-initialized at load and
// reset by the last block per o each launch (graph-replay safe).
__device__ float4 g_statsT[BC_];        // [c][b] -> (T, R0, C0, x00)
__device__ float4 g_wcatT[CO_];         // [o][c] -> (Wsum, -Wkh0, -Wkw0, W00)
__device__ float  g_part[QSPLIT][O_][B_];
__device__ unsigned int g_done[O_];

// ---------------------------------------------------------------------------
// Kernel A: fused stats (blocks 0..8191) + weight folding (blocks 8192..8447).
// Stats: one block per (b,c) 16 KB image, 256 threads, 4x float4 (__ldcs).
// 134 MB streaming read — the roofline kernel (~74% DRAM).
// ---------------------------------------------------------------------------
__global__ void __launch_bounds__(256) fused_prep_kernel(const float* __restrict__ x,
                                                         const float* __restrict__ w) {
    if (blockIdx.x < BC_) {
        const int bc = blockIdx.x;
        const float4* __restrict__ p4 =
            reinterpret_cast<const float4*>(x + (size_t)bc * HW_);
        const int t = threadIdx.x;

        float s = 0.f, r0 = 0.f, c0 = 0.f, v00 = 0.f;

        #pragma unroll
        for (int i = 0; i < 4; i++) {
            const int j = t + i * 256;        // float4 index 0..1023
            float4 v = __ldcs(&p4[j]);        // streaming: read-once data
            float vs = v.x + v.y + v.z + v.w;
            s += vs;
            if (j < 16)          r0 += vs;    // row 0 = first 64 elems
            if ((j & 15) == 0)   c0 += v.x;   // col 0 = elem % 64 == 0
            if (j == 0)          v00 = v.x;
        }

        #pragma unroll
        for (int off = 16; off > 0; off >>= 1) {
            s  += __shfl_xor_sync(0xFFFFFFFFu, s,  off);
            r0 += __shfl_xor_sync(0xFFFFFFFFu, r0, off);
            c0 += __shfl_xor_sync(0xFFFFFFFFu, c0, off);
        }

        __shared__ float ss[8], sr[8], sc[8];
        __shared__ float sv00;
        const int warp = t >> 5, lane = t & 31;
        if (t == 0) sv00 = v00;
        if (lane == 0) { ss[warp] = s; sr[warp] = r0; sc[warp] = c0; }
        __syncthreads();

        if (warp == 0) {
            float fs = (lane < 8) ? ss[lane] : 0.f;
            float fr = (lane < 8) ? sr[lane] : 0.f;
            float fc = (lane < 8) ? sc[lane] : 0.f;
            #pragma unroll
            for (int off = 4; off > 0; off >>= 1) {
                fs += __shfl_xor_sync(0xFFFFFFFFu, fs, off);
                fr += __shfl_xor_sync(0xFFFFFFFFu, fr, off);
                fc += __shfl_xor_sync(0xFFFFFFFFu, fc, off);
            }
            if (lane == 0) {
                const int b = bc >> 8;
                const int c = bc & 255;
                g_statsT[c * B_ + b] = make_float4(fs, fr, fc, sv00);
            }
        }
    } else {
        // ---------------- weight folding ----------------------------------
        const int i = (blockIdx.x - BC_) * 256 + threadIdx.x;   // i = c*256 + o
        const int c = i >> 8;
        const int o = i & 255;
        const float* p = w + (size_t)i * 9;
        float w00 = p[0], w01 = p[1], w02 = p[2];
        float w10 = p[3], w11 = p[4], w12 = p[5];
        float w20 = p[6], w21 = p[7], w22 = p[8];
        float wsum = ((w00 + w01) + (w02 + w10)) + ((w11 + w12) + (w20 + w21)) + w22;
        float wkh0 = w00 + w01 + w02;   // kh == 0 row
        float wkw0 = w00 + w10 + w20;   // kw == 0 col
        g_wcatT[o * C_ + c] = make_float4(wsum, -wkh0, -wkw0, w00);
    }
}

// ---------------------------------------------------------------------------
// Kernel B: split-c micro-GEMM. grid = 1024 blocks = (o, q), q in [0,4).
// Block (o,q) reduces channels [q*64, q*64+64):
//   lane = b, warp = 8-channel subgroup; smem-reduce -> g_part[q][o][b].
// Last-arriving block per o (threadfence-reduction pattern) combines the
// 4 partials, applies 2*(S/16384 + bias), writes out, resets the counter.
// ---------------------------------------------------------------------------
__global__ void __launch_bounds__(256) gemm_kernel(const float* __restrict__ bias,
                                                   float* __restrict__ out) {
    const int o = blockIdx.x >> 2;
    const int q = blockIdx.x & 3;
    const int t = threadIdx.x;

    __shared__ float4 wsm[CQ_];
    __shared__ float  red[8][33];
    __shared__ unsigned int s_old;

    if (t < CQ_) wsm[t] = g_wcatT[o * C_ + q * CQ_ + t];
    __syncthreads();

    const int b  = t & 31;   // lane = batch
    const int cg = t >> 5;   // warp = 8-channel subgroup
    const int cbase = q * CQ_ + cg * 8;

    float acc0 = 0.f, acc1 = 0.f;

    #pragma unroll
    for (int k = 0; k < 8; k += 2) {
        const int c = cbase + k;
        float4 a0 = g_statsT[c * B_ + b];
        float4 w0 = wsm[cg * 8 + k];
        float4 a1 = g_statsT[(c + 1) * B_ + b];
        float4 w1 = wsm[cg * 8 + k + 1];
        acc0 = fmaf(a0.x, w0.x, acc0);
        acc1 = fmaf(a1.x, w1.x, acc1);
        acc0 = fmaf(a0.y, w0.y, acc0);
        acc1 = fmaf(a1.y, w1.y, acc1);
        acc0 = fmaf(a0.z, w0.z, acc0);
        acc1 = fmaf(a1.z, w1.z, acc1);
        acc0 = fmaf(a0.w, w0.w, acc0);
        acc1 = fmaf(a1.w, w1.w, acc1);
    }

    red[cg][b] = acc0 + acc1;
    __syncthreads();

    if (cg == 0) {
        float s = 0.f;
        #pragma unroll
        for (int g = 0; g < 8; g++) s += red[g][b];
        g_part[q][o][b] = s;          // coalesced 128 B store
    }
    __syncthreads();

    // last-block election (release: fence before counter bump)
    if (t == 0) {
        __threadfence();
        s_old = atomicAdd(&g_done[o], 1u);
    }
    __syncthreads();

    if (s_old == QSPLIT - 1u) {       // this block arrived last for this o
        if (t < B_) {
            // __ldcg: bypass L1, read the L2-coherent partials
            float s = __ldcg(&g_part[0][o][t]) + __ldcg(&g_part[1][o][t])
                    + __ldcg(&g_part[2][o][t]) + __ldcg(&g_part[3][o][t]);
            out[t * O_ + o] = 2.0f * (s * (1.0f / 16384.0f) + bias[o]);
        }
        if (t == 0) atomicExch(&g_done[o], 0u);   // replay-safe reset
    }
}

// ---------------------------------------------------------------------------
extern "C" void kernel_launch(void* const* d_in, const int* in_sizes, int n_in,
                              void* d_out, int out_size) {
    const float* x    = (const float*)d_in[0];
    const float* wgt  = (const float*)d_in[1];
    const float* bias = (const float*)d_in[2];
    float* out        = (float*)d_out;

    fused_prep_kernel<<<BC_ + WPREP_BLOCKS, 256>>>(x, wgt);
    gemm_kernel<<<O_ * QSPLIT, 256>>>(bias, out);
}